// round 12
// baseline (speedup 1.0000x reference)
#include <cuda_runtime.h>
#include <cuda_bf16.h>
#include <cstdint>
#include <math.h>

#define E_ 1024
#define H_ 16
#define D_ 64
#define Q_ 4
#define B_ 4
#define S_ 2048
#define M_ (B_ * S_)        // 8192

// GEMM tiling: 128x256 block, BK=32, 16 warps (2m x 8n), warp tile 64x32
#define BM 128
#define BN 256
#define BK 32
#define NC (E_ / BK)        // 32 k-chunks
#define STAGES 4
#define STAGE_BYTES 49152   // Ah 8K | Al 8K | Bh 16K | Bl 16K
#define SMEM_REQ (STAGES * STAGE_BYTES)   // 192 KB

// ---------------- scratch (device globals: allocation-free) ----------------
__device__ __nv_bfloat16 g_xh[(size_t)M_ * E_];
__device__ __nv_bfloat16 g_xl[(size_t)M_ * E_];
__device__ __nv_bfloat16 g_wh[(size_t)7 * E_ * E_];   // Wq(4EE) | Wk | Wv | Wo
__device__ __nv_bfloat16 g_wl[(size_t)7 * E_ * E_];
__device__ __nv_bfloat16 g_zh[(size_t)M_ * E_];
__device__ __nv_bfloat16 g_zl[(size_t)M_ * E_];
__device__ float g_q[(size_t)Q_ * M_ * E_];
__device__ float g_k[(size_t)M_ * E_];
__device__ float g_v[(size_t)M_ * E_];

// ---------------- PTX helpers (baseline ISA only) ----------------
__device__ __forceinline__ uint32_t smem_u32(const void* p) {
    uint32_t a;
    asm("{ .reg .u64 t; cvta.to.shared.u64 t, %1; cvt.u32.u64 %0, t; }" : "=r"(a) : "l"(p));
    return a;
}
// XOR swizzle for 64B rows of 4x16B chunks: conflict-free ldmatrix phases
__device__ __forceinline__ uint32_t sw(int row, int ch) {
    return (uint32_t)(row * 64 + ((ch ^ ((row >> 1) & 3)) << 4));
}
#define CP16(dst, src) asm volatile("cp.async.cg.shared.global [%0], [%1], 16;" :: "r"(dst), "l"(src))
#define CP_COMMIT() asm volatile("cp.async.commit_group;" ::: "memory")
#define CP_WAIT2() asm volatile("cp.async.wait_group 2;" ::: "memory")
#define CP_WAIT1() asm volatile("cp.async.wait_group 1;" ::: "memory")
#define CP_WAIT0() asm volatile("cp.async.wait_group 0;" ::: "memory")

#define LDSM4(r0, r1, r2, r3, a) \
    asm volatile("ldmatrix.sync.aligned.m8n8.x4.shared.b16 {%0,%1,%2,%3}, [%4];" \
                 : "=r"(r0), "=r"(r1), "=r"(r2), "=r"(r3) : "r"(a))

#define MMA_BF16(d, a, b) \
    asm volatile("mma.sync.aligned.m16n8k16.row.col.f32.bf16.bf16.f32 " \
                 "{%0,%1,%2,%3}, {%4,%5,%6,%7}, {%8,%9}, {%0,%1,%2,%3};" \
                 : "+f"((d)[0]), "+f"((d)[1]), "+f"((d)[2]), "+f"((d)[3]) \
                 : "r"((a)[0]), "r"((a)[1]), "r"((a)[2]), "r"((a)[3]), \
                   "r"((b)[0]), "r"((b)[1]))

// ---------------------------------------------------------------------------
// fp32 -> bf16 hi/lo split
// ---------------------------------------------------------------------------
__global__ __launch_bounds__(256) void cvt_kernel(const float* __restrict__ s,
                                                  __nv_bfloat16* __restrict__ h,
                                                  __nv_bfloat16* __restrict__ l, int n4)
{
    int i = blockIdx.x * blockDim.x + threadIdx.x;
    if (i >= n4) return;
    float4 v = ((const float4*)s)[i];
    __nv_bfloat16 h0 = __float2bfloat16(v.x), h1 = __float2bfloat16(v.y);
    __nv_bfloat16 h2 = __float2bfloat16(v.z), h3 = __float2bfloat16(v.w);
    __nv_bfloat16 l0 = __float2bfloat16(v.x - __bfloat162float(h0));
    __nv_bfloat16 l1 = __float2bfloat16(v.y - __bfloat162float(h1));
    __nv_bfloat16 l2 = __float2bfloat16(v.z - __bfloat162float(h2));
    __nv_bfloat16 l3 = __float2bfloat16(v.w - __bfloat162float(h3));
    ((__nv_bfloat162*)h)[2 * i]     = __nv_bfloat162(h0, h1);
    ((__nv_bfloat162*)h)[2 * i + 1] = __nv_bfloat162(h2, h3);
    ((__nv_bfloat162*)l)[2 * i]     = __nv_bfloat162(l0, l1);
    ((__nv_bfloat162*)l)[2 * i + 1] = __nv_bfloat162(l2, l3);
}

// ---------------------------------------------------------------------------
// mma.sync bf16 GEMM, 3-term hi/lo split.
// Mainloop: ONE barrier per chunk; 4-stage cp.async pipeline; fragment
// loads split into (ah,bh) -> hh-MMAs -> (al,bl) -> hl/lh-MMAs for overlap.
// ---------------------------------------------------------------------------
__device__ __forceinline__ void gemm_mma(const __nv_bfloat16* __restrict__ Ah,
                                         const __nv_bfloat16* __restrict__ Al,
                                         const __nv_bfloat16* __restrict__ Bh,
                                         const __nv_bfloat16* __restrict__ Bl,
                                         const float* __restrict__ bias,
                                         float* __restrict__ C)
{
    extern __shared__ char dsmem[];
    const uint32_t sb = smem_u32(dsmem);
    const int tid  = threadIdx.x;
    const int lane = tid & 31;
    const int wid  = tid >> 5;            // 0..15
    const int mBase = (wid & 1) * 64;     // warp m-offset within 128
    const int nBase = (wid >> 1) * 32;    // warp n-offset within 256
    const int rowBase = blockIdx.y * BM;
    const int colBase = blockIdx.x * BN;

    // cp.async assignments (512 threads)
    const int ldrA = tid >> 2, ldcA = tid & 3;
    const int ldrB = tid >> 1, ldcB = tid & 1;
    const __nv_bfloat16* gAh = Ah + (size_t)(rowBase + ldrA) * E_;
    const __nv_bfloat16* gAl = Al + (size_t)(rowBase + ldrA) * E_;
    const __nv_bfloat16* gBh = Bh + (size_t)(colBase + ldrB) * E_;
    const __nv_bfloat16* gBl = Bl + (size_t)(colBase + ldrB) * E_;
    const uint32_t swA0 = sw(ldrA, ldcA);
    const uint32_t swB0 = sw(ldrB, ldcB);
    const uint32_t swB1 = sw(ldrB, ldcB + 2);

#define ISSUE(kc, st) do {                                                   \
    uint32_t bse = sb + (uint32_t)(st) * STAGE_BYTES;                        \
    int k0 = (kc) * BK;                                                      \
    CP16(bse + swA0,         gAh + k0 + ldcA * 8);                           \
    CP16(bse +  8192 + swA0, gAl + k0 + ldcA * 8);                           \
    CP16(bse + 16384 + swB0, gBh + k0 + ldcB * 8);                           \
    CP16(bse + 16384 + swB1, gBh + k0 + ldcB * 8 + 16);                      \
    CP16(bse + 32768 + swB0, gBl + k0 + ldcB * 8);                           \
    CP16(bse + 32768 + swB1, gBl + k0 + ldcB * 8 + 16);                      \
    CP_COMMIT();                                                             \
} while (0)

    float d[4][4][4];
#pragma unroll
    for (int i = 0; i < 4; ++i)
#pragma unroll
        for (int j = 0; j < 4; ++j)
#pragma unroll
            for (int k = 0; k < 4; ++k) d[i][j][k] = 0.f;

    // ldmatrix lane addressing (fixed per thread)
    const int aRow = mBase + (lane & 15);
    const int aCh  = lane >> 4;
    const int bRow = nBase + (lane & 7) + ((lane >> 4) << 3);
    const int bCh  = (lane >> 3) & 1;

    ISSUE(0, 0);
    ISSUE(1, 1);
    ISSUE(2, 2);

#pragma unroll 1
    for (int c = 0; c < NC; ++c) {
        // wait for chunk c's cp.async group (in flight: c, c+1, c+2 at most)
        if (c + 2 < NC)      { CP_WAIT2(); }
        else if (c + 1 < NC) { CP_WAIT1(); }
        else                 { CP_WAIT0(); }
        // Single barrier: (a) chunk-c data visible to all warps,
        // (b) all warps done reading stage (c+3)%4 (they read it at iter c-1).
        __syncthreads();
        if (c + 3 < NC) ISSUE(c + 3, (c + 3) & 3);

        const uint32_t bse = sb + (uint32_t)(c & 3) * STAGE_BYTES;
#pragma unroll
        for (int ks = 0; ks < 2; ++ks) {
            // pass 1: hi*hi
            uint32_t ah[4][4], bh[4][2];
#pragma unroll
            for (int mf = 0; mf < 4; ++mf) {
                uint32_t a = bse + sw(aRow + mf * 16, ks * 2 + aCh);
                LDSM4(ah[mf][0], ah[mf][1], ah[mf][2], ah[mf][3], a);
            }
#pragma unroll
            for (int t = 0; t < 2; ++t) {
                uint32_t a = bse + 16384 + sw(bRow + t * 16, ks * 2 + bCh);
                LDSM4(bh[2 * t][0], bh[2 * t][1], bh[2 * t + 1][0], bh[2 * t + 1][1], a);
            }
#pragma unroll
            for (int mf = 0; mf < 4; ++mf)
#pragma unroll
                for (int nf = 0; nf < 4; ++nf)
                    MMA_BF16(d[mf][nf], ah[mf], bh[nf]);

            // pass 2: lo fragments load under pass-1 MMAs, then hl + lh
            uint32_t al[4][4], bl[4][2];
#pragma unroll
            for (int mf = 0; mf < 4; ++mf) {
                uint32_t a = bse + 8192 + sw(aRow + mf * 16, ks * 2 + aCh);
                LDSM4(al[mf][0], al[mf][1], al[mf][2], al[mf][3], a);
            }
#pragma unroll
            for (int t = 0; t < 2; ++t) {
                uint32_t a = bse + 32768 + sw(bRow + t * 16, ks * 2 + bCh);
                LDSM4(bl[2 * t][0], bl[2 * t][1], bl[2 * t + 1][0], bl[2 * t + 1][1], a);
            }
#pragma unroll
            for (int mf = 0; mf < 4; ++mf)
#pragma unroll
                for (int nf = 0; nf < 4; ++nf)
                    MMA_BF16(d[mf][nf], ah[mf], bl[nf]);
#pragma unroll
            for (int mf = 0; mf < 4; ++mf)
#pragma unroll
                for (int nf = 0; nf < 4; ++nf)
                    MMA_BF16(d[mf][nf], al[mf], bh[nf]);
        }
        // no tail barrier: top-of-next-iteration barrier provides it
    }

    // epilogue
    const int r0 = rowBase + mBase + (lane >> 2);
    const int c0 = colBase + nBase + (lane & 3) * 2;
#pragma unroll
    for (int nf = 0; nf < 4; ++nf) {
        const int cc = c0 + nf * 8;
        const float b0 = bias[cc], b1 = bias[cc + 1];
#pragma unroll
        for (int mf = 0; mf < 4; ++mf) {
            const int rr = r0 + mf * 16;
            *(float2*)&C[(size_t)rr * E_ + cc] =
                make_float2(d[mf][nf][0] + b0, d[mf][nf][1] + b1);
            *(float2*)&C[(size_t)(rr + 8) * E_ + cc] =
                make_float2(d[mf][nf][2] + b0, d[mf][nf][3] + b1);
        }
    }
#undef ISSUE
}

__global__ __launch_bounds__(512, 1) void qkv_gemm(
    const float* __restrict__ bq, const float* __restrict__ bk, const float* __restrict__ bv)
{
    const int z = blockIdx.z;
    const __nv_bfloat16 *Bh, *Bl;
    const float* bias;
    float* C;
    const size_t EE = (size_t)E_ * E_;
    if (z < Q_)      { Bh = g_wh + z * EE; Bl = g_wl + z * EE; bias = bq + z * E_; C = g_q + (size_t)z * M_ * E_; }
    else if (z == Q_){ Bh = g_wh + 4 * EE; Bl = g_wl + 4 * EE; bias = bk; C = g_k; }
    else             { Bh = g_wh + 5 * EE; Bl = g_wl + 5 * EE; bias = bv; C = g_v; }
    gemm_mma(g_xh, g_xl, Bh, Bl, bias, C);
}

__global__ __launch_bounds__(512, 1) void out_gemm(
    const float* __restrict__ bo, float* __restrict__ out)
{
    const size_t EE = (size_t)E_ * E_;
    gemm_mma(g_zh, g_zl, g_wh + 6 * EE, g_wl + 6 * EE, bo, out);
}

// ---------------------------------------------------------------------------
// Per-token attention over heads (fp32); writes z as bf16 hi/lo in
// (B,H,S,D)-contiguous order == reference transpose+view for free.
// ---------------------------------------------------------------------------
__global__ __launch_bounds__(256) void attn_kernel()
{
    const int t   = blockIdx.x;
    const int b   = t / S_;
    const int s   = t - b * S_;
    const int tid = threadIdx.x;
    const int h   = tid >> 4;
    const int d0  = (tid & 15) << 2;

    __shared__ float sk[H_][D_ + 4];
    __shared__ float sv[H_][D_ + 4];
    __shared__ float sq[H_][D_ + 4];
    __shared__ float sp[H_][H_ + 1];

    {
        float4 k4 = *(const float4*)&g_k[(size_t)t * E_ + h * D_ + d0];
        float4 v4 = *(const float4*)&g_v[(size_t)t * E_ + h * D_ + d0];
        sk[h][d0 + 0] = k4.x; sk[h][d0 + 1] = k4.y; sk[h][d0 + 2] = k4.z; sk[h][d0 + 3] = k4.w;
        sv[h][d0 + 0] = v4.x; sv[h][d0 + 1] = v4.y; sv[h][d0 + 2] = v4.z; sv[h][d0 + 3] = v4.w;
    }

    float zo[4] = {0.f, 0.f, 0.f, 0.f};

    for (int qi = 0; qi < Q_; ++qi) {
        float4 q4 = *(const float4*)&g_q[((size_t)qi * M_ + t) * E_ + h * D_ + d0];
        sq[h][d0 + 0] = q4.x; sq[h][d0 + 1] = q4.y;
        sq[h][d0 + 2] = q4.z; sq[h][d0 + 3] = q4.w;
        __syncthreads();

        {
            const int g = tid & 15;
            const float* qr = sq[h];
            const float* kr = sk[g];
            float dot = 0.f;
#pragma unroll
            for (int dd = 0; dd < D_; ++dd) dot = fmaf(qr[dd], kr[dd], dot);
            sp[h][g] = dot * 0.125f;
        }
        __syncthreads();

        if (tid < H_) {
            float mx = -1e30f;
#pragma unroll
            for (int g = 0; g < H_; ++g) mx = fmaxf(mx, sp[tid][g]);
            float e[H_];
            float sum = 0.f;
#pragma unroll
            for (int g = 0; g < H_; ++g) { e[g] = expf(sp[tid][g] - mx); sum += e[g]; }
            float inv = 1.f / sum;
#pragma unroll
            for (int g = 0; g < H_; ++g) sp[tid][g] = e[g] * inv;
        }
        __syncthreads();

#pragma unroll
        for (int g = 0; g < H_; ++g) {
            float p = sp[h][g];
            zo[0] = fmaf(p, sv[g][d0 + 0], zo[0]);
            zo[1] = fmaf(p, sv[g][d0 + 1], zo[1]);
            zo[2] = fmaf(p, sv[g][d0 + 2], zo[2]);
            zo[3] = fmaf(p, sv[g][d0 + 3], zo[3]);
        }
    }

    size_t zidx = (((size_t)(b * H_ + h) * S_) + s) * D_ + d0;
    __nv_bfloat16 h0 = __float2bfloat16(zo[0]), h1 = __float2bfloat16(zo[1]);
    __nv_bfloat16 h2 = __float2bfloat16(zo[2]), h3 = __float2bfloat16(zo[3]);
    __nv_bfloat16 l0 = __float2bfloat16(zo[0] - __bfloat162float(h0));
    __nv_bfloat16 l1 = __float2bfloat16(zo[1] - __bfloat162float(h1));
    __nv_bfloat16 l2 = __float2bfloat16(zo[2] - __bfloat162float(h2));
    __nv_bfloat16 l3 = __float2bfloat16(zo[3] - __bfloat162float(h3));
    *(__nv_bfloat162*)&g_zh[zidx]     = __nv_bfloat162(h0, h1);
    *(__nv_bfloat162*)&g_zh[zidx + 2] = __nv_bfloat162(h2, h3);
    *(__nv_bfloat162*)&g_zl[zidx]     = __nv_bfloat162(l0, l1);
    *(__nv_bfloat162*)&g_zl[zidx + 2] = __nv_bfloat162(l2, l3);
}

// ---------------------------------------------------------------------------
extern "C" void kernel_launch(void* const* d_in, const int* in_sizes, int n_in,
                              void* d_out, int out_size)
{
    const float* x  = (const float*)d_in[0];
    const float* Wq = (const float*)d_in[1];
    const float* bq = (const float*)d_in[2];
    const float* Wk = (const float*)d_in[3];
    const float* bk = (const float*)d_in[4];
    const float* Wv = (const float*)d_in[5];
    const float* bv = (const float*)d_in[6];
    const float* Wo = (const float*)d_in[7];
    const float* bo = (const float*)d_in[8];
    float* out = (float*)d_out;

    cudaFuncSetAttribute(qkv_gemm, cudaFuncAttributeMaxDynamicSharedMemorySize, SMEM_REQ);
    cudaFuncSetAttribute(out_gemm, cudaFuncAttributeMaxDynamicSharedMemorySize, SMEM_REQ);

    __nv_bfloat16 *xh, *xl, *wh, *wl;
    cudaGetSymbolAddress((void**)&xh, g_xh);
    cudaGetSymbolAddress((void**)&xl, g_xl);
    cudaGetSymbolAddress((void**)&wh, g_wh);
    cudaGetSymbolAddress((void**)&wl, g_wl);

    const size_t EE = (size_t)E_ * E_;
    {
        int n4 = (M_ * E_) / 4;
        cvt_kernel<<<(n4 + 255) / 256, 256>>>(x, xh, xl, n4);
        n4 = (Q_ * EE) / 4;
        cvt_kernel<<<(n4 + 255) / 256, 256>>>(Wq, wh, wl, n4);
        n4 = EE / 4;
        cvt_kernel<<<(n4 + 255) / 256, 256>>>(Wk, wh + 4 * EE, wl + 4 * EE, n4);
        cvt_kernel<<<(n4 + 255) / 256, 256>>>(Wv, wh + 5 * EE, wl + 5 * EE, n4);
        cvt_kernel<<<(n4 + 255) / 256, 256>>>(Wo, wh + 6 * EE, wl + 6 * EE, n4);
    }

    dim3 gQKV(E_ / BN, M_ / BM, 6);     // 4 x 64 x 6
    qkv_gemm<<<gQKV, 512, SMEM_REQ>>>(bq, bk, bv);

    attn_kernel<<<M_, 256>>>();

    dim3 gOut(E_ / BN, M_ / BM, 1);
    out_gemm<<<gOut, 512, SMEM_REQ>>>(bo, out);
}

// round 15
// speedup vs baseline: 1.7708x; 1.7708x over previous
#include <cuda_runtime.h>
#include <cuda_bf16.h>
#include <cstdint>
#include <math.h>

#define E_ 1024
#define H_ 16
#define D_ 64
#define Q_ 4
#define B_ 4
#define S_ 2048
#define M_ (B_ * S_)        // 8192

// GEMM tiling: 128x128 block, BK=32, 8 warps (2m x 4n), warp tile 64x32
// 2 CTAs/SM: 96KB smem + ~120 regs/thread each.
#define BM 128
#define BN 128
#define BK 32
#define NC (E_ / BK)        // 32 k-chunks
#define STAGES 3
#define STAGE_BYTES 32768   // Ah 8K | Al 8K | Bh 8K | Bl 8K
#define SMEM_REQ (STAGES * STAGE_BYTES)   // 96 KB

// ---------------- scratch (device globals: allocation-free) ----------------
__device__ __nv_bfloat16 g_xh[(size_t)M_ * E_];
__device__ __nv_bfloat16 g_xl[(size_t)M_ * E_];
__device__ __nv_bfloat16 g_wh[(size_t)7 * E_ * E_];   // Wq(4EE) | Wk | Wv | Wo
__device__ __nv_bfloat16 g_wl[(size_t)7 * E_ * E_];
__device__ __nv_bfloat16 g_zh[(size_t)M_ * E_];
__device__ __nv_bfloat16 g_zl[(size_t)M_ * E_];
__device__ float g_q[(size_t)Q_ * M_ * E_];
__device__ float g_k[(size_t)M_ * E_];
__device__ float g_v[(size_t)M_ * E_];

// ---------------- PTX helpers (baseline ISA only) ----------------
__device__ __forceinline__ uint32_t smem_u32(const void* p) {
    uint32_t a;
    asm("{ .reg .u64 t; cvta.to.shared.u64 t, %1; cvt.u32.u64 %0, t; }" : "=r"(a) : "l"(p));
    return a;
}
// XOR swizzle for 64B rows of 4x16B chunks: conflict-free ldmatrix phases
__device__ __forceinline__ uint32_t sw(int row, int ch) {
    return (uint32_t)(row * 64 + ((ch ^ ((row >> 1) & 3)) << 4));
}
#define CP16(dst, src) asm volatile("cp.async.cg.shared.global [%0], [%1], 16;" :: "r"(dst), "l"(src))
#define CP_COMMIT() asm volatile("cp.async.commit_group;" ::: "memory")
#define CP_WAIT1() asm volatile("cp.async.wait_group 1;" ::: "memory")
#define CP_WAIT0() asm volatile("cp.async.wait_group 0;" ::: "memory")

#define LDSM4(r0, r1, r2, r3, a) \
    asm volatile("ldmatrix.sync.aligned.m8n8.x4.shared.b16 {%0,%1,%2,%3}, [%4];" \
                 : "=r"(r0), "=r"(r1), "=r"(r2), "=r"(r3) : "r"(a))

#define MMA_BF16(d, a, b) \
    asm volatile("mma.sync.aligned.m16n8k16.row.col.f32.bf16.bf16.f32 " \
                 "{%0,%1,%2,%3}, {%4,%5,%6,%7}, {%8,%9}, {%0,%1,%2,%3};" \
                 : "+f"((d)[0]), "+f"((d)[1]), "+f"((d)[2]), "+f"((d)[3]) \
                 : "r"((a)[0]), "r"((a)[1]), "r"((a)[2]), "r"((a)[3]), \
                   "r"((b)[0]), "r"((b)[1]))

// ---------------------------------------------------------------------------
// fp32 -> bf16 hi/lo split
// ---------------------------------------------------------------------------
__global__ __launch_bounds__(256) void cvt_kernel(const float* __restrict__ s,
                                                  __nv_bfloat16* __restrict__ h,
                                                  __nv_bfloat16* __restrict__ l, int n4)
{
    int i = blockIdx.x * blockDim.x + threadIdx.x;
    if (i >= n4) return;
    float4 v = ((const float4*)s)[i];
    __nv_bfloat16 h0 = __float2bfloat16(v.x), h1 = __float2bfloat16(v.y);
    __nv_bfloat16 h2 = __float2bfloat16(v.z), h3 = __float2bfloat16(v.w);
    __nv_bfloat16 l0 = __float2bfloat16(v.x - __bfloat162float(h0));
    __nv_bfloat16 l1 = __float2bfloat16(v.y - __bfloat162float(h1));
    __nv_bfloat16 l2 = __float2bfloat16(v.z - __bfloat162float(h2));
    __nv_bfloat16 l3 = __float2bfloat16(v.w - __bfloat162float(h3));
    ((__nv_bfloat162*)h)[2 * i]     = __nv_bfloat162(h0, h1);
    ((__nv_bfloat162*)h)[2 * i + 1] = __nv_bfloat162(h2, h3);
    ((__nv_bfloat162*)l)[2 * i]     = __nv_bfloat162(l0, l1);
    ((__nv_bfloat162*)l)[2 * i + 1] = __nv_bfloat162(l2, l3);
}

// ---------------------------------------------------------------------------
// mma.sync bf16 GEMM, 3-term hi/lo split, term-major ordering, split
// fragment loads. Proven R7 mainloop structure (wait -> sync -> issue ->
// compute -> sync), 3 stages, at 128x128/256thr for 2 CTAs/SM.
// ---------------------------------------------------------------------------
__device__ __forceinline__ void gemm_mma(const __nv_bfloat16* __restrict__ Ah,
                                         const __nv_bfloat16* __restrict__ Al,
                                         const __nv_bfloat16* __restrict__ Bh,
                                         const __nv_bfloat16* __restrict__ Bl,
                                         const float* __restrict__ bias,
                                         float* __restrict__ C)
{
    extern __shared__ char dsmem[];
    const uint32_t sb = smem_u32(dsmem);
    const int tid  = threadIdx.x;
    const int lane = tid & 31;
    const int wid  = tid >> 5;            // 0..7
    const int mBase = (wid & 1) * 64;     // warp m-offset within 128
    const int nBase = (wid >> 1) * 32;    // warp n-offset within 128
    const int rowBase = blockIdx.y * BM;
    const int colBase = blockIdx.x * BN;

    // cp.async: thread t -> tile row t>>1 (0..127), chunks {t&1, (t&1)+2}
    const int ldr = tid >> 1;
    const int ldc = tid & 1;
    const __nv_bfloat16* gAh = Ah + (size_t)(rowBase + ldr) * E_;
    const __nv_bfloat16* gAl = Al + (size_t)(rowBase + ldr) * E_;
    const __nv_bfloat16* gBh = Bh + (size_t)(colBase + ldr) * E_;
    const __nv_bfloat16* gBl = Bl + (size_t)(colBase + ldr) * E_;
    const uint32_t sw0 = sw(ldr, ldc);
    const uint32_t sw1 = sw(ldr, ldc + 2);

#define ISSUE(kc, st) do {                                                   \
    uint32_t bse = sb + (uint32_t)(st) * STAGE_BYTES;                        \
    int k0 = (kc) * BK;                                                      \
    CP16(bse + sw0,         gAh + k0 + ldc * 8);                             \
    CP16(bse + sw1,         gAh + k0 + ldc * 8 + 16);                        \
    CP16(bse +  8192 + sw0, gAl + k0 + ldc * 8);                             \
    CP16(bse +  8192 + sw1, gAl + k0 + ldc * 8 + 16);                        \
    CP16(bse + 16384 + sw0, gBh + k0 + ldc * 8);                             \
    CP16(bse + 16384 + sw1, gBh + k0 + ldc * 8 + 16);                        \
    CP16(bse + 24576 + sw0, gBl + k0 + ldc * 8);                             \
    CP16(bse + 24576 + sw1, gBl + k0 + ldc * 8 + 16);                        \
    CP_COMMIT();                                                             \
} while (0)

    float d[4][4][4];
#pragma unroll
    for (int i = 0; i < 4; ++i)
#pragma unroll
        for (int j = 0; j < 4; ++j)
#pragma unroll
            for (int k = 0; k < 4; ++k) d[i][j][k] = 0.f;

    // ldmatrix lane addressing (fixed per thread)
    const int aRow = mBase + (lane & 15);
    const int aCh  = lane >> 4;
    const int bRow = nBase + (lane & 7) + ((lane >> 4) << 3);
    const int bCh  = (lane >> 3) & 1;

    ISSUE(0, 0);
    ISSUE(1, 1);

    int stage = 0;
#pragma unroll 1
    for (int c = 0; c < NC; ++c) {
        if (c + 1 < NC) { CP_WAIT1(); } else { CP_WAIT0(); }
        __syncthreads();
        if (c + 2 < NC) {
            int st = stage + 2; if (st >= STAGES) st -= STAGES;
            ISSUE(c + 2, st);
        }

        const uint32_t bse = sb + (uint32_t)stage * STAGE_BYTES;
#pragma unroll
        for (int ks = 0; ks < 2; ++ks) {
            // pass 1: hi fragments + hh MMAs
            uint32_t ah[4][4], bh[4][2];
#pragma unroll
            for (int mf = 0; mf < 4; ++mf) {
                uint32_t a = bse + sw(aRow + mf * 16, ks * 2 + aCh);
                LDSM4(ah[mf][0], ah[mf][1], ah[mf][2], ah[mf][3], a);
            }
#pragma unroll
            for (int t = 0; t < 2; ++t) {
                uint32_t a = bse + 16384 + sw(bRow + t * 16, ks * 2 + bCh);
                LDSM4(bh[2 * t][0], bh[2 * t][1], bh[2 * t + 1][0], bh[2 * t + 1][1], a);
            }
#pragma unroll
            for (int mf = 0; mf < 4; ++mf)
#pragma unroll
                for (int nf = 0; nf < 4; ++nf)
                    MMA_BF16(d[mf][nf], ah[mf], bh[nf]);

            // pass 2: lo fragments load under pass-1 MMAs, then hl + lh
            uint32_t al[4][4], bl[4][2];
#pragma unroll
            for (int mf = 0; mf < 4; ++mf) {
                uint32_t a = bse + 8192 + sw(aRow + mf * 16, ks * 2 + aCh);
                LDSM4(al[mf][0], al[mf][1], al[mf][2], al[mf][3], a);
            }
#pragma unroll
            for (int t = 0; t < 2; ++t) {
                uint32_t a = bse + 24576 + sw(bRow + t * 16, ks * 2 + bCh);
                LDSM4(bl[2 * t][0], bl[2 * t][1], bl[2 * t + 1][0], bl[2 * t + 1][1], a);
            }
#pragma unroll
            for (int mf = 0; mf < 4; ++mf)
#pragma unroll
                for (int nf = 0; nf < 4; ++nf)
                    MMA_BF16(d[mf][nf], ah[mf], bl[nf]);
#pragma unroll
            for (int mf = 0; mf < 4; ++mf)
#pragma unroll
                for (int nf = 0; nf < 4; ++nf)
                    MMA_BF16(d[mf][nf], al[mf], bh[nf]);
        }
        __syncthreads();
        if (++stage >= STAGES) stage = 0;
    }

    // epilogue
    const int r0 = rowBase + mBase + (lane >> 2);
    const int c0 = colBase + nBase + (lane & 3) * 2;
#pragma unroll
    for (int nf = 0; nf < 4; ++nf) {
        const int cc = c0 + nf * 8;
        const float b0 = bias[cc], b1 = bias[cc + 1];
#pragma unroll
        for (int mf = 0; mf < 4; ++mf) {
            const int rr = r0 + mf * 16;
            *(float2*)&C[(size_t)rr * E_ + cc] =
                make_float2(d[mf][nf][0] + b0, d[mf][nf][1] + b1);
            *(float2*)&C[(size_t)(rr + 8) * E_ + cc] =
                make_float2(d[mf][nf][2] + b0, d[mf][nf][3] + b1);
        }
    }
#undef ISSUE
}

__global__ __launch_bounds__(256, 2) void qkv_gemm(
    const float* __restrict__ bq, const float* __restrict__ bk, const float* __restrict__ bv)
{
    const int z = blockIdx.z;
    const __nv_bfloat16 *Bh, *Bl;
    const float* bias;
    float* C;
    const size_t EE = (size_t)E_ * E_;
    if (z < Q_)      { Bh = g_wh + z * EE; Bl = g_wl + z * EE; bias = bq + z * E_; C = g_q + (size_t)z * M_ * E_; }
    else if (z == Q_){ Bh = g_wh + 4 * EE; Bl = g_wl + 4 * EE; bias = bk; C = g_k; }
    else             { Bh = g_wh + 5 * EE; Bl = g_wl + 5 * EE; bias = bv; C = g_v; }
    gemm_mma(g_xh, g_xl, Bh, Bl, bias, C);
}

__global__ __launch_bounds__(256, 2) void out_gemm(
    const float* __restrict__ bo, float* __restrict__ out)
{
    const size_t EE = (size_t)E_ * E_;
    gemm_mma(g_zh, g_zl, g_wh + 6 * EE, g_wl + 6 * EE, bo, out);
}

// ---------------------------------------------------------------------------
// Per-token attention over heads (fp32); writes z as bf16 hi/lo in
// (B,H,S,D)-contiguous order == reference transpose+view for free.
// ---------------------------------------------------------------------------
__global__ __launch_bounds__(256) void attn_kernel()
{
    const int t   = blockIdx.x;
    const int b   = t / S_;
    const int s   = t - b * S_;
    const int tid = threadIdx.x;
    const int h   = tid >> 4;
    const int d0  = (tid & 15) << 2;

    __shared__ float sk[H_][D_ + 4];
    __shared__ float sv[H_][D_ + 4];
    __shared__ float sq[H_][D_ + 4];
    __shared__ float sp[H_][H_ + 1];

    {
        float4 k4 = *(const float4*)&g_k[(size_t)t * E_ + h * D_ + d0];
        float4 v4 = *(const float4*)&g_v[(size_t)t * E_ + h * D_ + d0];
        sk[h][d0 + 0] = k4.x; sk[h][d0 + 1] = k4.y; sk[h][d0 + 2] = k4.z; sk[h][d0 + 3] = k4.w;
        sv[h][d0 + 0] = v4.x; sv[h][d0 + 1] = v4.y; sv[h][d0 + 2] = v4.z; sv[h][d0 + 3] = v4.w;
    }

    float zo[4] = {0.f, 0.f, 0.f, 0.f};

    for (int qi = 0; qi < Q_; ++qi) {
        float4 q4 = *(const float4*)&g_q[((size_t)qi * M_ + t) * E_ + h * D_ + d0];
        sq[h][d0 + 0] = q4.x; sq[h][d0 + 1] = q4.y;
        sq[h][d0 + 2] = q4.z; sq[h][d0 + 3] = q4.w;
        __syncthreads();

        {
            const int g = tid & 15;
            const float* qr = sq[h];
            const float* kr = sk[g];
            float dot = 0.f;
#pragma unroll
            for (int dd = 0; dd < D_; ++dd) dot = fmaf(qr[dd], kr[dd], dot);
            sp[h][g] = dot * 0.125f;
        }
        __syncthreads();

        if (tid < H_) {
            float mx = -1e30f;
#pragma unroll
            for (int g = 0; g < H_; ++g) mx = fmaxf(mx, sp[tid][g]);
            float e[H_];
            float sum = 0.f;
#pragma unroll
            for (int g = 0; g < H_; ++g) { e[g] = expf(sp[tid][g] - mx); sum += e[g]; }
            float inv = 1.f / sum;
#pragma unroll
            for (int g = 0; g < H_; ++g) sp[tid][g] = e[g] * inv;
        }
        __syncthreads();

#pragma unroll
        for (int g = 0; g < H_; ++g) {
            float p = sp[h][g];
            zo[0] = fmaf(p, sv[g][d0 + 0], zo[0]);
            zo[1] = fmaf(p, sv[g][d0 + 1], zo[1]);
            zo[2] = fmaf(p, sv[g][d0 + 2], zo[2]);
            zo[3] = fmaf(p, sv[g][d0 + 3], zo[3]);
        }
    }

    size_t zidx = (((size_t)(b * H_ + h) * S_) + s) * D_ + d0;
    __nv_bfloat16 h0 = __float2bfloat16(zo[0]), h1 = __float2bfloat16(zo[1]);
    __nv_bfloat16 h2 = __float2bfloat16(zo[2]), h3 = __float2bfloat16(zo[3]);
    __nv_bfloat16 l0 = __float2bfloat16(zo[0] - __bfloat162float(h0));
    __nv_bfloat16 l1 = __float2bfloat16(zo[1] - __bfloat162float(h1));
    __nv_bfloat16 l2 = __float2bfloat16(zo[2] - __bfloat162float(h2));
    __nv_bfloat16 l3 = __float2bfloat16(zo[3] - __bfloat162float(h3));
    *(__nv_bfloat162*)&g_zh[zidx]     = __nv_bfloat162(h0, h1);
    *(__nv_bfloat162*)&g_zh[zidx + 2] = __nv_bfloat162(h2, h3);
    *(__nv_bfloat162*)&g_zl[zidx]     = __nv_bfloat162(l0, l1);
    *(__nv_bfloat162*)&g_zl[zidx + 2] = __nv_bfloat162(l2, l3);
}

// ---------------------------------------------------------------------------
extern "C" void kernel_launch(void* const* d_in, const int* in_sizes, int n_in,
                              void* d_out, int out_size)
{
    const float* x  = (const float*)d_in[0];
    const float* Wq = (const float*)d_in[1];
    const float* bq = (const float*)d_in[2];
    const float* Wk = (const float*)d_in[3];
    const float* bk = (const float*)d_in[4];
    const float* Wv = (const float*)d_in[5];
    const float* bv = (const float*)d_in[6];
    const float* Wo = (const float*)d_in[7];
    const float* bo = (const float*)d_in[8];
    float* out = (float*)d_out;

    cudaFuncSetAttribute(qkv_gemm, cudaFuncAttributeMaxDynamicSharedMemorySize, SMEM_REQ);
    cudaFuncSetAttribute(out_gemm, cudaFuncAttributeMaxDynamicSharedMemorySize, SMEM_REQ);

    __nv_bfloat16 *xh, *xl, *wh, *wl;
    cudaGetSymbolAddress((void**)&xh, g_xh);
    cudaGetSymbolAddress((void**)&xl, g_xl);
    cudaGetSymbolAddress((void**)&wh, g_wh);
    cudaGetSymbolAddress((void**)&wl, g_wl);

    const size_t EE = (size_t)E_ * E_;
    {
        int n4 = (M_ * E_) / 4;
        cvt_kernel<<<(n4 + 255) / 256, 256>>>(x, xh, xl, n4);
        n4 = (Q_ * EE) / 4;
        cvt_kernel<<<(n4 + 255) / 256, 256>>>(Wq, wh, wl, n4);
        n4 = EE / 4;
        cvt_kernel<<<(n4 + 255) / 256, 256>>>(Wk, wh + 4 * EE, wl + 4 * EE, n4);
        cvt_kernel<<<(n4 + 255) / 256, 256>>>(Wv, wh + 5 * EE, wl + 5 * EE, n4);
        cvt_kernel<<<(n4 + 255) / 256, 256>>>(Wo, wh + 6 * EE, wl + 6 * EE, n4);
    }

    dim3 gQKV(E_ / BN, M_ / BM, 6);     // 8 x 64 x 6
    qkv_gemm<<<gQKV, 256, SMEM_REQ>>>(bq, bk, bv);

    attn_kernel<<<M_, 256>>>();

    dim3 gOut(E_ / BN, M_ / BM, 1);
    out_gemm<<<gOut, 256, SMEM_REQ>>>(bo, out);
}